// round 1
// baseline (speedup 1.0000x reference)
#include <cuda_runtime.h>
#include <cuda_bf16.h>

// TopKPool: scores = E·w + b (masked), top-k=8 per row, mean-pool selected rows,
// indicator attn weights. B=128, K=512, D=768.
// Output layout: [pooled (B*D) | attn_weights (B*K)], fp32.

#define NEG_INF (-1e30f)
#define SENTINEL (-2e30f)

constexpr int Bv = 128;
constexpr int Kv = 512;
constexpr int Dv = 768;
constexpr int THREADS = 1024;   // 32 warps
constexpr int MAX_TOPK = 64;

__global__ __launch_bounds__(THREADS, 1)
void topkpool_fused(const float* __restrict__ emb,
                    const int*   __restrict__ mask,
                    const float* __restrict__ w,
                    const float* __restrict__ bias,
                    const int*   __restrict__ topk,
                    float*       __restrict__ out)
{
    __shared__ __align__(16) float s_w[Dv];
    __shared__ float s_sc[Kv];
    __shared__ float s_rv[32];
    __shared__ int   s_ri[32];
    __shared__ int   s_top[MAX_TOPK];

    const int b    = blockIdx.x;
    const int tid  = threadIdx.x;
    const int lane = tid & 31;
    const int wid  = tid >> 5;

    // --- load scorer weight into smem ---
    for (int i = tid; i < Dv; i += THREADS) s_w[i] = w[i];
    __syncthreads();

    const float bval = bias[0];
    const float* eb = emb + (size_t)b * Kv * Dv;

    // --- phase 1: scores (warp-per-row dot products, float4 coalesced) ---
    const float4* wv = (const float4*)s_w;
    for (int k = wid; k < Kv; k += 32) {
        const float4* row = (const float4*)(eb + (size_t)k * Dv);
        float acc = 0.f;
        #pragma unroll
        for (int j = 0; j < 6; j++) {
            float4 e  = row[j * 32 + lane];
            float4 ww = wv [j * 32 + lane];
            acc += e.x * ww.x + e.y * ww.y + e.z * ww.z + e.w * ww.w;
        }
        #pragma unroll
        for (int off = 16; off; off >>= 1)
            acc += __shfl_xor_sync(0xFFFFFFFFu, acc, off);
        if (lane == 0) {
            float s = acc + bval;
            if (mask[(size_t)b * Kv + k] == 0) s = NEG_INF;
            s_sc[k] = s;
        }
    }
    __syncthreads();

    int ksel = topk[0];
    if (ksel > Kv) ksel = Kv;
    if (ksel < 1)  ksel = 1;
    if (ksel > MAX_TOPK) ksel = MAX_TOPK;

    float* out_pool = out;                       // (B, D)
    float* out_attn = out + (size_t)Bv * Dv;     // (B, K)

    // zero this row's attn weights (d_out is poisoned)
    for (int i = tid; i < Kv; i += THREADS)
        out_attn[(size_t)b * Kv + i] = 0.f;

    // --- phase 2: top-k via ksel parallel argmax passes ---
    for (int m = 0; m < ksel; m++) {
        float v = SENTINEL;
        int   idx = Kv;                          // tie-break: lowest index wins
        if (tid < Kv) { v = s_sc[tid]; idx = tid; }
        #pragma unroll
        for (int off = 16; off; off >>= 1) {
            float v2 = __shfl_xor_sync(0xFFFFFFFFu, v, off);
            int   i2 = __shfl_xor_sync(0xFFFFFFFFu, idx, off);
            if (v2 > v || (v2 == v && i2 < idx)) { v = v2; idx = i2; }
        }
        if (lane == 0) { s_rv[wid] = v; s_ri[wid] = idx; }
        __syncthreads();
        if (wid == 0) {
            float v3 = s_rv[lane];
            int   i3 = s_ri[lane];
            #pragma unroll
            for (int off = 16; off; off >>= 1) {
                float v2 = __shfl_xor_sync(0xFFFFFFFFu, v3, off);
                int   i2 = __shfl_xor_sync(0xFFFFFFFFu, i3, off);
                if (v2 > v3 || (v2 == v3 && i2 < i3)) { v3 = v2; i3 = i2; }
            }
            if (lane == 0) {
                s_top[m]  = i3;
                s_sc[i3]  = SENTINEL;            // knock out for next pass
            }
        }
        __syncthreads();
    }

    // --- phase 3: indicator weights + mean pooling ---
    const float inv = 1.f / (float)ksel;
    if (tid < ksel)
        out_attn[(size_t)b * Kv + s_top[tid]] = inv;

    for (int c = tid; c < Dv; c += THREADS) {
        float sum = 0.f;
        #pragma unroll 4
        for (int m = 0; m < ksel; m++)
            sum += eb[(size_t)s_top[m] * Dv + c];
        out_pool[(size_t)b * Dv + c] = sum * inv;
    }
}

extern "C" void kernel_launch(void* const* d_in, const int* in_sizes, int n_in,
                              void* d_out, int out_size)
{
    const float* emb  = (const float*)d_in[0];
    const int*   mask = (const int*)  d_in[1];
    const float* w    = (const float*)d_in[2];
    const float* bias = (const float*)d_in[3];
    const int*   topk = (const int*)  d_in[4];
    float*       out  = (float*)d_out;
    (void)in_sizes; (void)n_in; (void)out_size;

    topkpool_fused<<<Bv, THREADS>>>(emb, mask, w, bias, topk, out);
}